// round 7
// baseline (speedup 1.0000x reference)
#include <cuda_runtime.h>
#include <cuda_bf16.h>
#include <cstdint>

// DySample: x(8,256,64,64), W_off(32,256), b_off(32) -> out(8,256,128,128), fp32.
//   A: offsets = W_off @ x + b_off folded into final sample coords -> 4MB scratch.
//      2-position register blocking: one smem W read feeds 2 positions.
//   B: bilinear gather staged through smem with replicated border columns
//      (branch-free x handling); 3-row window with global fallback for y.
// ix = w + (0.25*off_x + ipx), iy = h + (0.25*off_y + ipy);
// j = g*4 + ry*2 + rx; o_x = j, o_y = 16 + j; ipx = (j&1)?+.25:-.25, ipy = ((j>>1)&1)?+.25:-.25

#define Bn 8
#define Cn 256
#define Hn 64
#define Wn 64
#define Gn 4
#define NPOS 4096
#define OH 128
#define OW 128
#define XPAD 68   // [0] unused, [1]=col0, [2..65]=cols 0..63, [66]=[67]=col63

typedef unsigned long long ull;

__device__ float d_coord[Bn * 32 * NPOS];   // 4 MB scratch

__device__ __forceinline__ void ffma2(ull &d, ull a, ull b) {
    asm("fma.rn.f32x2 %0, %1, %2, %0;" : "+l"(d) : "l"(a), "l"(b));
}
__device__ __forceinline__ ull pack2(float lo, float hi) {
    ull r;
    asm("mov.b64 %0, {%1, %2};" : "=l"(r) : "f"(lo), "f"(hi));
    return r;
}
__device__ __forceinline__ void unpack2(ull v, float &lo, float &hi) {
    asm("mov.b64 {%0, %1}, %2;" : "=f"(lo), "=f"(hi) : "l"(v));
}

// ---------------- Kernel A: offset GEMM, 8-way channel split, 2 pos/thread ----
// grid (64, 8), 256 threads. Block = 64 positions; thread = (posl, cq) handles
// positions posl and posl+32, channels cq*32..cq*32+31.
__global__ __launch_bounds__(256) void offset_kernel(
    const float* __restrict__ x,
    const float* __restrict__ Woff,
    const float* __restrict__ boff)
{
    __shared__ __align__(16) char sraw[32768];
    ull (*Wp)[256] = reinterpret_cast<ull(*)[256]>(sraw);            // [16][256] 32KB
    float2 (*red)[8][32] = reinterpret_cast<float2(*)[8][32]>(sraw); // [16][8][32] 32KB

    const int tid  = threadIdx.x;
    const int b    = blockIdx.y;
    const int posl = tid & 31;
    const int cq   = tid >> 5;                 // 0..7 (warp-uniform)
    const int gpos0 = blockIdx.x * 64 + posl;
    const int gpos1 = gpos0 + 32;

    #pragma unroll
    for (int i = 0; i < 16; i++) {
        const int idx = i * 256 + tid;
        const int p = idx >> 8, c = idx & 255;
        Wp[p][c] = pack2(Woff[p * Cn + c], Woff[(p + 16) * Cn + c]);
    }
    __syncthreads();

    ull acc0[16], acc1[16];
    #pragma unroll
    for (int p = 0; p < 16; p++) { acc0[p] = 0ull; acc1[p] = 0ull; }

    const float* xb = x + (size_t)b * Cn * NPOS;
    const int c0 = cq * 32;

    #pragma unroll 2
    for (int cc = 0; cc < 32; cc += 2) {
        const int c = c0 + cc;
        const float* pc0 = xb + (size_t)c * NPOS;
        const float* pc1 = xb + (size_t)(c + 1) * NPOS;
        const float xa0 = __ldg(pc0 + gpos0);
        const float xa1 = __ldg(pc0 + gpos1);
        const float xb0 = __ldg(pc1 + gpos0);
        const float xb1 = __ldg(pc1 + gpos1);
        const ull xpa0 = pack2(xa0, xa0);
        const ull xpa1 = pack2(xa1, xa1);
        const ull xpb0 = pack2(xb0, xb0);
        const ull xpb1 = pack2(xb1, xb1);
        #pragma unroll
        for (int p = 0; p < 16; p++) {
            ulonglong2 wv = *(const ulonglong2*)&Wp[p][c];
            ffma2(acc0[p], wv.x, xpa0);
            ffma2(acc1[p], wv.x, xpa1);
            ffma2(acc0[p], wv.y, xpb0);
            ffma2(acc1[p], wv.y, xpb1);
        }
    }
    __syncthreads();                      // Wp dead; reuse smem

    const int pp = tid >> 5;

    // ---- pass over both position halves ----
    #pragma unroll
    for (int half = 0; half < 2; half++) {
        const int gpos = half ? gpos1 : gpos0;
        #pragma unroll
        for (int p = 0; p < 16; p++) {
            float lo, hi;
            unpack2(half ? acc1[p] : acc0[p], lo, hi);
            red[p][cq][posl] = make_float2(lo, hi);
        }
        __syncthreads();

        const int w = gpos & 63;
        const int h = gpos >> 6;
        #pragma unroll
        for (int t = 0; t < 2; t++) {
            const int p = pp * 2 + t;
            float2 s = red[p][0][posl];
            #pragma unroll
            for (int q = 1; q < 8; q++) {
                float2 u = red[p][q][posl];
                s.x += u.x; s.y += u.y;
            }
            const float ipx = (p & 1) ? 0.25f : -0.25f;
            const float ipy = ((p >> 1) & 1) ? 0.25f : -0.25f;
            const float cx = (float)w + 0.25f * (s.x + __ldg(boff + p)) + ipx;
            const float cy = (float)h + 0.25f * (s.y + __ldg(boff + p + 16)) + ipy;
            d_coord[(size_t)(b * 32 + p) * NPOS + gpos]      = cx;
            d_coord[(size_t)(b * 32 + p + 16) * NPOS + gpos] = cy;
        }
        __syncthreads();
    }
}

// ---------------- Kernel B: smem-staged branch-free bilinear gather ----------
// grid (64, 8, 8) = (h, b, g*2+half). 256 threads. Stage 3 rows x 32 ch, padded.
__global__ __launch_bounds__(256) void gather_kernel(
    const float* __restrict__ x,
    float* __restrict__ out)
{
    __shared__ float xs[3][32][XPAD];   // ~25.5 KB, [row][c][paddedW]
    __shared__ float sxy[2][4][64];     // 2 KB,  [xy][jj][wq]

    const int tid  = threadIdx.x;
    const int h    = blockIdx.x;
    const int b    = blockIdx.y;
    const int g    = blockIdx.z >> 1;
    const int half = blockIdx.z & 1;

    // stage coords for this group's 4 j's
    #pragma unroll
    for (int i = 0; i < 2; i++) {
        const int lin = i * 256 + tid;        // 0..511
        const int w  = lin & 63;
        const int jj = (lin >> 6) & 3;
        const int xy = lin >> 8;
        sxy[xy][jj][w] =
            d_coord[(size_t)(b * 32 + g * 4 + jj + xy * 16) * NPOS + (h << 6) + w];
    }

    // stage 3 input rows (clamped) x 32 channels into columns [2..65]
    const int cstage = b * Cn + g * 64 + half * 32;
    #pragma unroll
    for (int i = 0; i < 6; i++) {
        const int lin = i * 256 + tid;        // 0..1535
        const int w4 = lin & 15;
        const int rr = (lin >> 4) % 3;
        const int c  = lin / 48;              // 0..31
        const int rowy = min(max(h - 1 + rr, 0), Hn - 1);
        const float4 v = __ldg((const float4*)(x
            + (((size_t)(cstage + c)) * Hn + rowy) * Wn) + w4);
        float* dst = &xs[rr][c][2 + w4 * 4];  // byte offset 8+16*w4 -> 8B aligned
        *(float2*)dst       = make_float2(v.x, v.y);
        *(float2*)(dst + 2) = make_float2(v.z, v.w);
    }
    // border replicas straight from gmem (96 (r,c) pairs)
    if (tid < 96) {
        const int rr = tid >> 5;              // 0..2
        const int c  = tid & 31;
        const int rowy = min(max(h - 1 + rr, 0), Hn - 1);
        const float* rowp = x + (((size_t)(cstage + c)) * Hn + rowy) * Wn;
        const float l = __ldg(rowp);
        const float r = __ldg(rowp + Wn - 1);
        xs[rr][c][1]  = l;
        xs[rr][c][66] = r;
        xs[rr][c][67] = r;
    }
    __syncthreads();

    const int ox    = tid & 127;
    const int chunk = tid >> 7;               // 0..1 -> 16 channels each
    const int wq = ox >> 1;
    const int rx = ox & 1;
    const int cbase = cstage + chunk * 16;

    #pragma unroll
    for (int ry = 0; ry < 2; ry++) {
        const int jj = ry * 2 + rx;
        float ix = sxy[0][jj][wq];
        float iy = sxy[1][jj][wq];
        ix = fminf(fmaxf(ix, -1.f), 64.f);    // border clamp: exact (wx moot outside)
        iy = fminf(fmaxf(iy, -1.f), 64.f);
        const float xf = floorf(ix);
        const float yf = floorf(iy);
        const float wx = ix - xf;
        const float wy = iy - yf;
        const int xi = (int)xf;               // [-1, 64]
        const int yi = (int)yf;               // [-1, 64]
        const int y0 = min(max(yi, 0), Hn - 1);
        const int y1 = min(max(yi + 1, 0), Hn - 1);
        const int r0 = y0 - h + 1;
        const int r1 = y1 - h + 1;
        const int idx = xi + 2;               // [1, 66]; read idx, idx+1
        const bool fast = ((unsigned)r0 <= 2u) && ((unsigned)r1 <= 2u);

        const int oy = 2 * h + ry;
        float* op = out + (((size_t)cbase * OH + oy) * OW + ox);

        if (__builtin_expect(fast, 1)) {
            const float* base0 = &xs[r0][chunk * 16][idx];
            const float* base1 = &xs[r1][chunk * 16][idx];
            #pragma unroll
            for (int k = 0; k < 16; k++) {
                const float a0 = base0[k * XPAD];
                const float a1 = base0[k * XPAD + 1];
                const float b0 = base1[k * XPAD];
                const float b1 = base1[k * XPAD + 1];
                const float top = a0 + wx * (a1 - a0);
                const float bot = b0 + wx * (b1 - b0);
                op[(size_t)k * (OH * OW)] = top + wy * (bot - top);
            }
        } else {
            const int x0 = min(max(xi, 0), Wn - 1);
            const int x1 = min(max(xi + 1, 0), Wn - 1);
            const int o00 = y0 * Wn + x0;
            const int o01 = y0 * Wn + x1;
            const int o10 = y1 * Wn + x0;
            const int o11 = y1 * Wn + x1;
            const float w0x = 1.f - wx, w1x = wx;
            const float w0y = 1.f - wy, w1y = wy;
            #pragma unroll
            for (int k = 0; k < 16; k++) {
                const float* p = x + (size_t)(cbase + k) * NPOS;
                const float v = (w0x * __ldg(p + o00) + w1x * __ldg(p + o01)) * w0y
                              + (w0x * __ldg(p + o10) + w1x * __ldg(p + o11)) * w1y;
                op[(size_t)k * (OH * OW)] = v;
            }
        }
    }
}

extern "C" void kernel_launch(void* const* d_in, const int* in_sizes, int n_in,
                              void* d_out, int out_size) {
    const float* x    = (const float*)d_in[0];
    const float* Woff = (const float*)d_in[1];
    const float* boff = (const float*)d_in[2];
    float* out = (float*)d_out;

    dim3 gridA(64, Bn);
    offset_kernel<<<gridA, 256>>>(x, Woff, boff);

    dim3 gridB(Hn, Bn, 8);
    gather_kernel<<<gridB, 256>>>(x, out);
}